// round 1
// baseline (speedup 1.0000x reference)
#include <cuda_runtime.h>
#include <math.h>

#define NN 100000
#define EE 1200000
#define HH 64
#define F_GAMMA (-0.45f)
#define F_ZETA  (1.05f)

// -------- scratch (no allocation allowed -> __device__ globals) ----------
__device__ float g_g1[NN * HH];     // per-node f1 @ att1_W_top
__device__ float g_g2[NN * HH];     // per-node f2 @ att1_W_bot + att1_b
__device__ float g_x[NN * HH];      // current x
__device__ float g_xnew[NN * HH];   // aggregated x for this layer
__device__ float g_mask[EE];        // per-edge gate
__device__ float g_rowsum[NN];
__device__ float g_dinv[NN];

// ------------------------ init: x = out = features ------------------------
__global__ void init_kernel(const float* __restrict__ feat,
                            float* __restrict__ x, float* __restrict__ out) {
    int n4 = NN * HH / 4;
    const float4* f4 = (const float4*)feat;
    float4* x4 = (float4*)x;
    float4* o4 = (float4*)out;
    for (int i = blockIdx.x * blockDim.x + threadIdx.x; i < n4;
         i += gridDim.x * blockDim.x) {
        float4 v = f4[i];
        x4[i] = v;
        o4[i] = v;
    }
}

// --------- per-node: f1,f2 (relu matvecs) then g1,g2 projections ----------
// 4 nodes per warp to amortize shared-memory weight reads.
// Also zeroes rowsum[] and xnew[] for this layer.
__global__ void __launch_bounds__(256) node_kernel(
    const float* __restrict__ x,
    const float* __restrict__ nbW,  const float* __restrict__ nbb,
    const float* __restrict__ sfW,  const float* __restrict__ sfb,
    const float* __restrict__ a1W,  const float* __restrict__ a1b,
    float* __restrict__ g1, float* __restrict__ g2,
    float* __restrict__ rowsum, float* __restrict__ xnew) {
    extern __shared__ float sm[];
    float* sNb  = sm;            // [64][64]
    float* sSf  = sm + 4096;
    float* sTop = sm + 8192;     // att1_W rows 0..63
    float* sBot = sm + 12288;    // att1_W rows 64..127

    for (int idx = threadIdx.x; idx < 4096; idx += blockDim.x) {
        sNb[idx]  = nbW[idx];
        sSf[idx]  = sfW[idx];
        sTop[idx] = a1W[idx];
        sBot[idx] = a1W[4096 + idx];
    }
    __syncthreads();

    const unsigned FULL = 0xffffffffu;
    int lane = threadIdx.x & 31;
    int warp = (blockIdx.x * blockDim.x + threadIdx.x) >> 5;
    int base = warp * 4;

    const float2* x2 = (const float2*)x;
    float2 xr[4];
    int   nid[4];
    bool  ok[4];
#pragma unroll
    for (int m = 0; m < 4; m++) {
        nid[m] = base + m;
        ok[m] = (nid[m] < NN);
        xr[m] = ok[m] ? x2[nid[m] * 32 + lane] : make_float2(0.f, 0.f);
    }

    // ---- f1 = relu(x@nbW + nbb), f2 = relu(x@sfW + sfb) ----
    float f1a[4], f1b[4], f2a[4], f2b[4];
    {
        float bn0 = nbb[lane], bn1 = nbb[lane + 32];
        float bs0 = sfb[lane], bs1 = sfb[lane + 32];
#pragma unroll
        for (int m = 0; m < 4; m++) { f1a[m]=bn0; f1b[m]=bn1; f2a[m]=bs0; f2b[m]=bs1; }
    }
#pragma unroll 8
    for (int k = 0; k < 64; k++) {
        float wn0 = sNb[k * 64 + lane], wn1 = sNb[k * 64 + 32 + lane];
        float ws0 = sSf[k * 64 + lane], ws1 = sSf[k * 64 + 32 + lane];
#pragma unroll
        for (int m = 0; m < 4; m++) {
            float xv = __shfl_sync(FULL, (k & 1) ? xr[m].y : xr[m].x, k >> 1);
            f1a[m] += xv * wn0; f1b[m] += xv * wn1;
            f2a[m] += xv * ws0; f2b[m] += xv * ws1;
        }
    }
#pragma unroll
    for (int m = 0; m < 4; m++) {
        f1a[m] = fmaxf(f1a[m], 0.f); f1b[m] = fmaxf(f1b[m], 0.f);
        f2a[m] = fmaxf(f2a[m], 0.f); f2b[m] = fmaxf(f2b[m], 0.f);
    }

    // ---- g1 = f1 @ Wtop ; g2 = f2 @ Wbot + a1b ----
    float g1a[4], g1b[4], g2a[4], g2b[4];
    {
        float ba0 = a1b[lane], ba1 = a1b[lane + 32];
#pragma unroll
        for (int m = 0; m < 4; m++) { g1a[m]=0.f; g1b[m]=0.f; g2a[m]=ba0; g2b[m]=ba1; }
    }
#pragma unroll 8
    for (int k = 0; k < 32; k++) {
        float wt0 = sTop[k * 64 + lane], wt1 = sTop[k * 64 + 32 + lane];
        float wb0 = sBot[k * 64 + lane], wb1 = sBot[k * 64 + 32 + lane];
#pragma unroll
        for (int m = 0; m < 4; m++) {
            float u = __shfl_sync(FULL, f1a[m], k);
            float v = __shfl_sync(FULL, f2a[m], k);
            g1a[m] += u * wt0; g1b[m] += u * wt1;
            g2a[m] += v * wb0; g2b[m] += v * wb1;
        }
    }
#pragma unroll 8
    for (int k = 32; k < 64; k++) {
        float wt0 = sTop[k * 64 + lane], wt1 = sTop[k * 64 + 32 + lane];
        float wb0 = sBot[k * 64 + lane], wb1 = sBot[k * 64 + 32 + lane];
#pragma unroll
        for (int m = 0; m < 4; m++) {
            float u = __shfl_sync(FULL, f1b[m], k - 32);
            float v = __shfl_sync(FULL, f2b[m], k - 32);
            g1a[m] += u * wt0; g1b[m] += u * wt1;
            g2a[m] += v * wb0; g2b[m] += v * wb1;
        }
    }

#pragma unroll
    for (int m = 0; m < 4; m++) {
        if (!ok[m]) continue;
        int o = nid[m] * 64;
        g1[o + lane] = g1a[m];      g1[o + 32 + lane] = g1b[m];
        g2[o + lane] = g2a[m];      g2[o + 32 + lane] = g2b[m];
        xnew[o + lane] = 0.f;       xnew[o + 32 + lane] = 0.f;
        if (lane == 0) rowsum[nid[m]] = 0.f;
    }
}

// ----------- per-edge attention: mask[e], rowsum accumulation -------------
__global__ void __launch_bounds__(256) attn_kernel(
    const float* __restrict__ g1, const float* __restrict__ g2,
    const float* __restrict__ a2W, const float* __restrict__ a2b,
    const int* __restrict__ row, const int* __restrict__ col,
    float* __restrict__ mask, float* __restrict__ rowsum) {
    const unsigned FULL = 0xffffffffu;
    int lane = threadIdx.x & 31;
    int warp = (blockIdx.x * blockDim.x + threadIdx.x) >> 5;
    int nwarp = (gridDim.x * blockDim.x) >> 5;
    float2 w = ((const float2*)a2W)[lane];
    float bias = a2b[0];
    const float2* g1v = (const float2*)g1;
    const float2* g2v = (const float2*)g2;
    for (int e = warp; e < EE; e += nwarp) {
        int r = __ldg(row + e);
        int c = __ldg(col + e);
        float2 a = g1v[r * 32 + lane];
        float2 b = g2v[c * 32 + lane];
        float p = fmaxf(a.x + b.x, 0.f) * w.x + fmaxf(a.y + b.y, 0.f) * w.y;
#pragma unroll
        for (int off = 16; off; off >>= 1) p += __shfl_xor_sync(FULL, p, off);
        if (lane == 0) {
            float la  = p + bias;
            float sig = 1.f / (1.f + expf(-la));
            float mk  = fminf(fmaxf(sig * (F_ZETA - F_GAMMA) + F_GAMMA, 0.f), 1.f);
            mask[e] = mk;
            atomicAdd(rowsum + r, mk);
        }
    }
}

// --------------------------- d^{-1/2} per node ----------------------------
__global__ void dinv_kernel(const float* __restrict__ rowsum,
                            float* __restrict__ dinv) {
    for (int i = blockIdx.x * blockDim.x + threadIdx.x; i < NN;
         i += gridDim.x * blockDim.x) {
        float d = rsqrtf(rowsum[i] + 1e-6f);
        dinv[i] = fminf(d, 10.f);
    }
}

// ------- SpMM: xnew[row] += mask*dinv[row]*dinv[col] * x[col] -------------
// 16 lanes per edge (float4 lanes), vector reductions to L2.
__global__ void __launch_bounds__(256) spmm_kernel(
    const float* __restrict__ x, const float* __restrict__ mask,
    const float* __restrict__ dinv,
    const int* __restrict__ row, const int* __restrict__ col,
    float* __restrict__ xnew) {
    int tid   = blockIdx.x * blockDim.x + threadIdx.x;
    int half  = tid >> 4;
    int ln    = tid & 15;
    int nhalf = (gridDim.x * blockDim.x) >> 4;
    const float4* x4 = (const float4*)x;
    for (int e = half; e < EE; e += nhalf) {
        int r = __ldg(row + e);
        int c = __ldg(col + e);
        float v = mask[e] * dinv[r] * dinv[c];
        float4 xv = x4[c * 16 + ln];
        float* dst = xnew + r * 64 + ln * 4;
        asm volatile("red.global.add.v4.f32 [%0], {%1,%2,%3,%4};"
                     :: "l"(dst), "f"(v * xv.x), "f"(v * xv.y),
                        "f"(v * xv.z), "f"(v * xv.w)
                     : "memory");
    }
}

// ------------------- x = xnew ; out += xnew (per layer) -------------------
__global__ void update_kernel(const float* __restrict__ xnew,
                              float* __restrict__ x, float* __restrict__ out) {
    int n4 = NN * HH / 4;
    const float4* s4 = (const float4*)xnew;
    float4* x4 = (float4*)x;
    float4* o4 = (float4*)out;
    for (int i = blockIdx.x * blockDim.x + threadIdx.x; i < n4;
         i += gridDim.x * blockDim.x) {
        float4 t = s4[i];
        x4[i] = t;
        float4 o = o4[i];
        o.x += t.x; o.y += t.y; o.z += t.z; o.w += t.w;
        o4[i] = o;
    }
}

extern "C" void kernel_launch(void* const* d_in, const int* in_sizes, int n_in,
                              void* d_out, int out_size) {
    const float* features = (const float*)d_in[0];
    const float* nb_W     = (const float*)d_in[1];
    const float* nb_b     = (const float*)d_in[2];
    const float* self_W   = (const float*)d_in[3];
    const float* self_b   = (const float*)d_in[4];
    const float* att1_W   = (const float*)d_in[5];
    const float* att1_b   = (const float*)d_in[6];
    const float* att2_W   = (const float*)d_in[7];
    const float* att2_b   = (const float*)d_in[8];
    const int*   row      = (const int*)d_in[9];
    const int*   col      = (const int*)d_in[10];
    float* out = (float*)d_out;

    float *g1, *g2, *x, *xnew, *mask, *rowsum, *dinv;
    cudaGetSymbolAddress((void**)&g1,     g_g1);
    cudaGetSymbolAddress((void**)&g2,     g_g2);
    cudaGetSymbolAddress((void**)&x,      g_x);
    cudaGetSymbolAddress((void**)&xnew,   g_xnew);
    cudaGetSymbolAddress((void**)&mask,   g_mask);
    cudaGetSymbolAddress((void**)&rowsum, g_rowsum);
    cudaGetSymbolAddress((void**)&dinv,   g_dinv);

    const int SMEM = 4 * 4096 * (int)sizeof(float);  // 64 KB weights
    cudaFuncSetAttribute(node_kernel,
                         cudaFuncAttributeMaxDynamicSharedMemorySize, SMEM);

    init_kernel<<<2048, 256>>>(features, x, out);

    for (int l = 0; l < 3; l++) {
        node_kernel<<<3125, 256, SMEM>>>(
            x,
            nb_W + l * 4096,  nb_b + l * 64,
            self_W + l * 4096, self_b + l * 64,
            att1_W + l * 8192, att1_b + l * 64,
            g1, g2, rowsum, xnew);
        attn_kernel<<<4096, 256>>>(g1, g2, att2_W + l * 64, att2_b + l,
                                   row, col, mask, rowsum);
        dinv_kernel<<<391, 256>>>(rowsum, dinv);
        spmm_kernel<<<4096, 256>>>(x, mask, dinv, row, col, xnew);
        update_kernel<<<2048, 256>>>(xnew, x, out);
    }
}

// round 3
// speedup vs baseline: 1.0685x; 1.0685x over previous
#include <cuda_runtime.h>
#include <math.h>

#define NN 100000
#define EE 1200000
#define F_GAMMA (-0.45f)
#define F_ZETA  (1.05f)

// ---------------- scratch (__device__ globals; no allocs allowed) ---------
__device__ float g_g1[NN * 64];
__device__ float g_g2[NN * 64];
__device__ float g_xa[NN * 64];
__device__ float g_xb[NN * 64];
__device__ float g_mask[EE];     // CSR order
__device__ float g_dinv[NN];
__device__ int   g_rowptr[NN + 1];
__device__ int   g_wptr[NN];
__device__ int   g_count[NN];
__device__ int   g_ecol[EE];     // CSR col indices

// --------------------------- CSR build ------------------------------------
__global__ void zero_count_k(int* __restrict__ count) {
    for (int i = blockIdx.x * blockDim.x + threadIdx.x; i < NN;
         i += gridDim.x * blockDim.x) count[i] = 0;
}

__global__ void hist_k(const int* __restrict__ row, int* __restrict__ count) {
    for (int e = blockIdx.x * blockDim.x + threadIdx.x; e < EE;
         e += gridDim.x * blockDim.x) atomicAdd(count + row[e], 1);
}

// single-block exclusive scan over NN counts -> rowptr, wptr
__global__ void __launch_bounds__(1024) scan_k(const int* __restrict__ count,
                                               int* __restrict__ rowptr,
                                               int* __restrict__ wptr) {
    __shared__ int s[1024];
    int t = threadIdx.x;
    const int CH = (NN + 1023) / 1024;           // 98
    int beg = t * CH;
    int end = beg + CH; if (end > NN) end = NN;
    int sum = 0;
    for (int i = beg; i < end; i++) sum += count[i];
    s[t] = sum;
    __syncthreads();
    for (int o = 1; o < 1024; o <<= 1) {
        int v = s[t];
        if (t >= o) v += s[t - o];
        __syncthreads();
        s[t] = v;
        __syncthreads();
    }
    int run = (t == 0) ? 0 : s[t - 1];
    for (int i = beg; i < end; i++) {
        rowptr[i] = run;
        wptr[i]   = run;
        run += count[i];
    }
    if (t == 1023) rowptr[NN] = EE;
}

__global__ void scatter_k(const int* __restrict__ row, const int* __restrict__ col,
                          int* __restrict__ wptr, int* __restrict__ ecol) {
    for (int e = blockIdx.x * blockDim.x + threadIdx.x; e < EE;
         e += gridDim.x * blockDim.x) {
        int r = row[e];
        int p = atomicAdd(wptr + r, 1);
        ecol[p] = col[e];
    }
}

// --------- per-node: f1,f2 (relu matvecs) then g1,g2 projections ----------
__global__ void __launch_bounds__(256) node_kernel(
    const float* __restrict__ x,
    const float* __restrict__ nbW,  const float* __restrict__ nbb,
    const float* __restrict__ sfW,  const float* __restrict__ sfb,
    const float* __restrict__ a1W,  const float* __restrict__ a1b,
    float* __restrict__ g1, float* __restrict__ g2) {
    extern __shared__ float sm[];
    float* sNb  = sm;            // [64][64]
    float* sSf  = sm + 4096;
    float* sTop = sm + 8192;     // att1_W rows 0..63
    float* sBot = sm + 12288;    // att1_W rows 64..127

    for (int idx = threadIdx.x; idx < 4096; idx += blockDim.x) {
        sNb[idx]  = nbW[idx];
        sSf[idx]  = sfW[idx];
        sTop[idx] = a1W[idx];
        sBot[idx] = a1W[4096 + idx];
    }
    __syncthreads();

    const unsigned FULL = 0xffffffffu;
    int lane = threadIdx.x & 31;
    int warp = (blockIdx.x * blockDim.x + threadIdx.x) >> 5;
    int base = warp * 4;

    const float2* x2 = (const float2*)x;
    float2 xr[4];
    int   nid[4];
    bool  ok[4];
#pragma unroll
    for (int m = 0; m < 4; m++) {
        nid[m] = base + m;
        ok[m] = (nid[m] < NN);
        xr[m] = ok[m] ? x2[nid[m] * 32 + lane] : make_float2(0.f, 0.f);
    }

    float f1a[4], f1b[4], f2a[4], f2b[4];
    {
        float bn0 = nbb[lane], bn1 = nbb[lane + 32];
        float bs0 = sfb[lane], bs1 = sfb[lane + 32];
#pragma unroll
        for (int m = 0; m < 4; m++) { f1a[m]=bn0; f1b[m]=bn1; f2a[m]=bs0; f2b[m]=bs1; }
    }
#pragma unroll 8
    for (int k = 0; k < 64; k++) {
        float wn0 = sNb[k * 64 + lane], wn1 = sNb[k * 64 + 32 + lane];
        float ws0 = sSf[k * 64 + lane], ws1 = sSf[k * 64 + 32 + lane];
#pragma unroll
        for (int m = 0; m < 4; m++) {
            float xv = __shfl_sync(FULL, (k & 1) ? xr[m].y : xr[m].x, k >> 1);
            f1a[m] += xv * wn0; f1b[m] += xv * wn1;
            f2a[m] += xv * ws0; f2b[m] += xv * ws1;
        }
    }
#pragma unroll
    for (int m = 0; m < 4; m++) {
        f1a[m] = fmaxf(f1a[m], 0.f); f1b[m] = fmaxf(f1b[m], 0.f);
        f2a[m] = fmaxf(f2a[m], 0.f); f2b[m] = fmaxf(f2b[m], 0.f);
    }

    float g1a[4], g1b[4], g2a[4], g2b[4];
    {
        float ba0 = a1b[lane], ba1 = a1b[lane + 32];
#pragma unroll
        for (int m = 0; m < 4; m++) { g1a[m]=0.f; g1b[m]=0.f; g2a[m]=ba0; g2b[m]=ba1; }
    }
#pragma unroll 8
    for (int k = 0; k < 32; k++) {
        float wt0 = sTop[k * 64 + lane], wt1 = sTop[k * 64 + 32 + lane];
        float wb0 = sBot[k * 64 + lane], wb1 = sBot[k * 64 + 32 + lane];
#pragma unroll
        for (int m = 0; m < 4; m++) {
            float u = __shfl_sync(FULL, f1a[m], k);
            float v = __shfl_sync(FULL, f2a[m], k);
            g1a[m] += u * wt0; g1b[m] += u * wt1;
            g2a[m] += v * wb0; g2b[m] += v * wb1;
        }
    }
#pragma unroll 8
    for (int k = 32; k < 64; k++) {
        float wt0 = sTop[k * 64 + lane], wt1 = sTop[k * 64 + 32 + lane];
        float wb0 = sBot[k * 64 + lane], wb1 = sBot[k * 64 + 32 + lane];
#pragma unroll
        for (int m = 0; m < 4; m++) {
            float u = __shfl_sync(FULL, f1b[m], k - 32);
            float v = __shfl_sync(FULL, f2b[m], k - 32);
            g1a[m] += u * wt0; g1b[m] += u * wt1;
            g2a[m] += v * wb0; g2b[m] += v * wb1;
        }
    }

#pragma unroll
    for (int m = 0; m < 4; m++) {
        if (!ok[m]) continue;
        int o = nid[m] * 64;
        g1[o + lane] = g1a[m];      g1[o + 32 + lane] = g1b[m];
        g2[o + lane] = g2a[m];      g2[o + 32 + lane] = g2b[m];
    }
}

// ------ attention, CSR warp-per-row: mask[p] + dinv[r], no atomics --------
__global__ void __launch_bounds__(256) attn_k(
    const float* __restrict__ g1, const float* __restrict__ g2,
    const float* __restrict__ a2W, const float* __restrict__ a2b,
    const int* __restrict__ rowptr, const int* __restrict__ ecol,
    float* __restrict__ mask, float* __restrict__ dinv) {
    const unsigned FULL = 0xffffffffu;
    int lane = threadIdx.x & 31;
    int r = (blockIdx.x * blockDim.x + threadIdx.x) >> 5;
    if (r >= NN) return;

    float2 w = ((const float2*)a2W)[lane];
    float bias = a2b[0];
    float2 a = ((const float2*)g1)[r * 32 + lane];
    const float2* g2v = (const float2*)g2;

    int p0 = __ldg(rowptr + r), p1 = __ldg(rowptr + r + 1);
    float rs = 0.f;
#pragma unroll 2
    for (int p = p0; p < p1; p++) {
        int c = __ldg(ecol + p);
        float2 b = g2v[c * 32 + lane];
        float s = fmaxf(a.x + b.x, 0.f) * w.x + fmaxf(a.y + b.y, 0.f) * w.y;
#pragma unroll
        for (int off = 16; off; off >>= 1) s += __shfl_xor_sync(FULL, s, off);
        float la  = s + bias;
        float sig = 1.f / (1.f + __expf(-la));
        float mk  = fminf(fmaxf(sig * (F_ZETA - F_GAMMA) + F_GAMMA, 0.f), 1.f);
        if (lane == 0) mask[p] = mk;
        rs += mk;
    }
    if (lane == 0) dinv[r] = fminf(rsqrtf(rs + 1e-6f), 10.f);
}

// --- SpMM CSR warp-per-row, register accumulate, fused (x=..., out+=) -----
__global__ void __launch_bounds__(256) spmm_k(
    const float* __restrict__ x, const float* __restrict__ mask,
    const float* __restrict__ dinv,
    const int* __restrict__ rowptr, const int* __restrict__ ecol,
    float* __restrict__ xnew, float* __restrict__ out) {
    int lane = threadIdx.x & 31;
    int r = (blockIdx.x * blockDim.x + threadIdx.x) >> 5;
    if (r >= NN) return;

    const float2* x2 = (const float2*)x;
    int p0 = __ldg(rowptr + r), p1 = __ldg(rowptr + r + 1);
    float ax = 0.f, ay = 0.f;
#pragma unroll 2
    for (int p = p0; p < p1; p++) {
        int c = __ldg(ecol + p);
        float v = __ldg(mask + p) * __ldg(dinv + c);
        float2 xv = x2[c * 32 + lane];
        ax += v * xv.x;
        ay += v * xv.y;
    }
    float dr = __ldg(dinv + r);
    ax *= dr; ay *= dr;
    ((float2*)xnew)[r * 32 + lane] = make_float2(ax, ay);
    float2 o = ((float2*)out)[r * 32 + lane];
    o.x += ax; o.y += ay;
    ((float2*)out)[r * 32 + lane] = o;
}

extern "C" void kernel_launch(void* const* d_in, const int* in_sizes, int n_in,
                              void* d_out, int out_size) {
    const float* features = (const float*)d_in[0];
    const float* nb_W     = (const float*)d_in[1];
    const float* nb_b     = (const float*)d_in[2];
    const float* self_W   = (const float*)d_in[3];
    const float* self_b   = (const float*)d_in[4];
    const float* att1_W   = (const float*)d_in[5];
    const float* att1_b   = (const float*)d_in[6];
    const float* att2_W   = (const float*)d_in[7];
    const float* att2_b   = (const float*)d_in[8];
    const int*   row      = (const int*)d_in[9];
    const int*   col      = (const int*)d_in[10];
    float* out = (float*)d_out;

    float *g1, *g2, *xa, *xb, *mask, *dinv;
    int *rowptr, *wptr, *count, *ecol;
    cudaGetSymbolAddress((void**)&g1,     g_g1);
    cudaGetSymbolAddress((void**)&g2,     g_g2);
    cudaGetSymbolAddress((void**)&xa,     g_xa);
    cudaGetSymbolAddress((void**)&xb,     g_xb);
    cudaGetSymbolAddress((void**)&mask,   g_mask);
    cudaGetSymbolAddress((void**)&dinv,   g_dinv);
    cudaGetSymbolAddress((void**)&rowptr, g_rowptr);
    cudaGetSymbolAddress((void**)&wptr,   g_wptr);
    cudaGetSymbolAddress((void**)&count,  g_count);
    cudaGetSymbolAddress((void**)&ecol,   g_ecol);

    const int SMEM = 4 * 4096 * (int)sizeof(float);  // 64 KB weights
    cudaFuncSetAttribute(node_kernel,
                         cudaFuncAttributeMaxDynamicSharedMemorySize, SMEM);

    // out = features (x for layer 0 is read directly from features)
    cudaMemcpyAsync(out, features, (size_t)NN * 64 * sizeof(float),
                    cudaMemcpyDeviceToDevice);

    // ---- CSR build (once; reused by all 3 layers) ----
    zero_count_k<<<391, 256>>>(count);
    hist_k<<<2048, 256>>>(row, count);
    scan_k<<<1, 1024>>>(count, rowptr, wptr);
    scatter_k<<<2048, 256>>>(row, col, wptr, ecol);

    const float* xin[3]  = { features, xa, xb };
    float*       xout[3] = { xa, xb, xa };

    for (int l = 0; l < 3; l++) {
        node_kernel<<<3125, 256, SMEM>>>(
            xin[l],
            nb_W + l * 4096,   nb_b + l * 64,
            self_W + l * 4096, self_b + l * 64,
            att1_W + l * 8192, att1_b + l * 64,
            g1, g2);
        attn_k<<<12500, 256>>>(g1, g2, att2_W + l * 64, att2_b + l,
                               rowptr, ecol, mask, dinv);
        spmm_k<<<12500, 256>>>(xin[l], mask, dinv, rowptr, ecol,
                               xout[l], out);
    }
}

// round 6
// speedup vs baseline: 1.2014x; 1.1244x over previous
#include <cuda_runtime.h>
#include <math.h>

#define NN 100000
#define EE 1200000
#define F_GAMMA (-0.45f)
#define F_ZETA  (1.05f)

// ---------------- scratch (__device__ globals; no allocs allowed) ---------
__device__ float g_g1[NN * 64];
__device__ float g_g2[NN * 64];
__device__ float g_xa[NN * 64];
__device__ float g_xb[NN * 64];
__device__ float g_mask[EE];     // CSR order
__device__ float g_dinv[NN];
__device__ int   g_rowptr[NN + 1];
__device__ int   g_wptr[NN];
__device__ int   g_count[NN];
__device__ int   g_ecol[EE];     // CSR col indices

// --------------------------- CSR build ------------------------------------
__global__ void hist_k(const int* __restrict__ row, int* __restrict__ count) {
    for (int e = blockIdx.x * blockDim.x + threadIdx.x; e < EE;
         e += gridDim.x * blockDim.x) atomicAdd(count + row[e], 1);
}

// single-block exclusive scan over NN counts -> rowptr, wptr
__global__ void __launch_bounds__(1024) scan_k(const int* __restrict__ count,
                                               int* __restrict__ rowptr,
                                               int* __restrict__ wptr) {
    __shared__ int s[1024];
    int t = threadIdx.x;
    const int CH = (NN + 1023) / 1024;           // 98
    int beg = t * CH;
    int end = beg + CH; if (end > NN) end = NN;
    int sum = 0;
    for (int i = beg; i < end; i++) sum += count[i];
    s[t] = sum;
    __syncthreads();
    for (int o = 1; o < 1024; o <<= 1) {
        int v = s[t];
        if (t >= o) v += s[t - o];
        __syncthreads();
        s[t] = v;
        __syncthreads();
    }
    int run = (t == 0) ? 0 : s[t - 1];
    for (int i = beg; i < end; i++) {
        rowptr[i] = run;
        wptr[i]   = run;
        run += count[i];
    }
    if (t == 1023) rowptr[NN] = EE;
}

__global__ void scatter_k(const int* __restrict__ row, const int* __restrict__ col,
                          int* __restrict__ wptr, int* __restrict__ ecol) {
    for (int e = blockIdx.x * blockDim.x + threadIdx.x; e < EE;
         e += gridDim.x * blockDim.x) {
        int r = row[e];
        int p = atomicAdd(wptr + r, 1);
        ecol[p] = col[e];
    }
}

// --------- per-node: f1,f2 (relu matvecs) then g1,g2 projections ----------
__global__ void __launch_bounds__(256) node_kernel(
    const float* __restrict__ x,
    const float* __restrict__ nbW,  const float* __restrict__ nbb,
    const float* __restrict__ sfW,  const float* __restrict__ sfb,
    const float* __restrict__ a1W,  const float* __restrict__ a1b,
    float* __restrict__ g1, float* __restrict__ g2) {
    extern __shared__ float sm[];
    float* sNb  = sm;            // [64][64]
    float* sSf  = sm + 4096;
    float* sTop = sm + 8192;     // att1_W rows 0..63
    float* sBot = sm + 12288;    // att1_W rows 64..127

    for (int idx = threadIdx.x; idx < 4096; idx += blockDim.x) {
        sNb[idx]  = nbW[idx];
        sSf[idx]  = sfW[idx];
        sTop[idx] = a1W[idx];
        sBot[idx] = a1W[4096 + idx];
    }
    __syncthreads();

    const unsigned FULL = 0xffffffffu;
    int lane = threadIdx.x & 31;
    int warp = (blockIdx.x * blockDim.x + threadIdx.x) >> 5;
    int base = warp * 4;

    const float2* x2 = (const float2*)x;
    float2 xr[4];
    int   nid[4];
    bool  ok[4];
#pragma unroll
    for (int m = 0; m < 4; m++) {
        nid[m] = base + m;
        ok[m] = (nid[m] < NN);
        xr[m] = ok[m] ? x2[nid[m] * 32 + lane] : make_float2(0.f, 0.f);
    }

    float f1a[4], f1b[4], f2a[4], f2b[4];
    {
        float bn0 = nbb[lane], bn1 = nbb[lane + 32];
        float bs0 = sfb[lane], bs1 = sfb[lane + 32];
#pragma unroll
        for (int m = 0; m < 4; m++) { f1a[m]=bn0; f1b[m]=bn1; f2a[m]=bs0; f2b[m]=bs1; }
    }
#pragma unroll 8
    for (int k = 0; k < 64; k++) {
        float wn0 = sNb[k * 64 + lane], wn1 = sNb[k * 64 + 32 + lane];
        float ws0 = sSf[k * 64 + lane], ws1 = sSf[k * 64 + 32 + lane];
#pragma unroll
        for (int m = 0; m < 4; m++) {
            float xv = __shfl_sync(FULL, (k & 1) ? xr[m].y : xr[m].x, k >> 1);
            f1a[m] += xv * wn0; f1b[m] += xv * wn1;
            f2a[m] += xv * ws0; f2b[m] += xv * ws1;
        }
    }
#pragma unroll
    for (int m = 0; m < 4; m++) {
        f1a[m] = fmaxf(f1a[m], 0.f); f1b[m] = fmaxf(f1b[m], 0.f);
        f2a[m] = fmaxf(f2a[m], 0.f); f2b[m] = fmaxf(f2b[m], 0.f);
    }

    float g1a[4], g1b[4], g2a[4], g2b[4];
    {
        float ba0 = a1b[lane], ba1 = a1b[lane + 32];
#pragma unroll
        for (int m = 0; m < 4; m++) { g1a[m]=0.f; g1b[m]=0.f; g2a[m]=ba0; g2b[m]=ba1; }
    }
#pragma unroll 8
    for (int k = 0; k < 32; k++) {
        float wt0 = sTop[k * 64 + lane], wt1 = sTop[k * 64 + 32 + lane];
        float wb0 = sBot[k * 64 + lane], wb1 = sBot[k * 64 + 32 + lane];
#pragma unroll
        for (int m = 0; m < 4; m++) {
            float u = __shfl_sync(FULL, f1a[m], k);
            float v = __shfl_sync(FULL, f2a[m], k);
            g1a[m] += u * wt0; g1b[m] += u * wt1;
            g2a[m] += v * wb0; g2b[m] += v * wb1;
        }
    }
#pragma unroll 8
    for (int k = 32; k < 64; k++) {
        float wt0 = sTop[k * 64 + lane], wt1 = sTop[k * 64 + 32 + lane];
        float wb0 = sBot[k * 64 + lane], wb1 = sBot[k * 64 + 32 + lane];
#pragma unroll
        for (int m = 0; m < 4; m++) {
            float u = __shfl_sync(FULL, f1b[m], k - 32);
            float v = __shfl_sync(FULL, f2b[m], k - 32);
            g1a[m] += u * wt0; g1b[m] += u * wt1;
            g2a[m] += v * wb0; g2b[m] += v * wb1;
        }
    }

#pragma unroll
    for (int m = 0; m < 4; m++) {
        if (!ok[m]) continue;
        int o = nid[m] * 64;
        g1[o + lane] = g1a[m];      g1[o + 32 + lane] = g1b[m];
        g2[o + lane] = g2a[m];      g2[o + 32 + lane] = g2b[m];
    }
}

// ---- attention, CSR warp-per-row, 2 edges/iter via half-warps (float4) ---
__global__ void __launch_bounds__(256) attn_k(
    const float* __restrict__ g1, const float* __restrict__ g2,
    const float* __restrict__ a2W, const float* __restrict__ a2b,
    const int* __restrict__ rowptr, const int* __restrict__ ecol,
    float* __restrict__ mask, float* __restrict__ dinv) {
    int lane = threadIdx.x & 31;
    int half = lane >> 4;
    int ln   = lane & 15;
    unsigned hm = 0xFFFFu << (half << 4);
    int r = (blockIdx.x * blockDim.x + threadIdx.x) >> 5;
    if (r >= NN) return;

    float4 w = ((const float4*)a2W)[ln];
    float bias = a2b[0];
    float4 a = ((const float4*)g1)[r * 16 + ln];
    const float4* g2v = (const float4*)g2;

    int p0 = __ldg(rowptr + r), p1 = __ldg(rowptr + r + 1);
    float rs = 0.f;
#pragma unroll 2
    for (int p = p0 + half; p < p1; p += 2) {
        int c = __ldg(ecol + p);
        float4 b = g2v[c * 16 + ln];
        float s = fmaxf(a.x + b.x, 0.f) * w.x
                + fmaxf(a.y + b.y, 0.f) * w.y
                + fmaxf(a.z + b.z, 0.f) * w.z
                + fmaxf(a.w + b.w, 0.f) * w.w;
        s += __shfl_xor_sync(hm, s, 8);
        s += __shfl_xor_sync(hm, s, 4);
        s += __shfl_xor_sync(hm, s, 2);
        s += __shfl_xor_sync(hm, s, 1);
        float sig = 1.f / (1.f + __expf(-(s + bias)));
        float mk  = fminf(fmaxf(sig * (F_ZETA - F_GAMMA) + F_GAMMA, 0.f), 1.f);
        if (ln == 0) mask[p] = mk;
        rs += mk;
    }
    rs += __shfl_xor_sync(0xffffffffu, rs, 16);
    if (lane == 0) dinv[r] = fminf(rsqrtf(rs + 1e-6f), 10.f);
}

// -- SpMM CSR warp-per-row, 2 edges/iter via half-warps, fused epilogue ----
__global__ void __launch_bounds__(256) spmm_k(
    const float* __restrict__ x, const float* __restrict__ mask,
    const float* __restrict__ dinv,
    const int* __restrict__ rowptr, const int* __restrict__ ecol,
    float* __restrict__ xnew, float* __restrict__ out) {
    const unsigned FULL = 0xffffffffu;
    int lane = threadIdx.x & 31;
    int half = lane >> 4;
    int ln   = lane & 15;
    int r = (blockIdx.x * blockDim.x + threadIdx.x) >> 5;
    if (r >= NN) return;

    const float4* x4 = (const float4*)x;
    int p0 = __ldg(rowptr + r), p1 = __ldg(rowptr + r + 1);
    float ax = 0.f, ay = 0.f, az = 0.f, aw = 0.f;
#pragma unroll 2
    for (int p = p0 + half; p < p1; p += 2) {
        int c = __ldg(ecol + p);
        float v = __ldg(mask + p) * __ldg(dinv + c);
        float4 xv = x4[c * 16 + ln];
        ax += v * xv.x; ay += v * xv.y; az += v * xv.z; aw += v * xv.w;
    }
    ax += __shfl_xor_sync(FULL, ax, 16);
    ay += __shfl_xor_sync(FULL, ay, 16);
    az += __shfl_xor_sync(FULL, az, 16);
    aw += __shfl_xor_sync(FULL, aw, 16);
    if (half == 0) {
        float dr = __ldg(dinv + r);
        float4 res = make_float4(ax * dr, ay * dr, az * dr, aw * dr);
        ((float4*)xnew)[r * 16 + ln] = res;
        float4 o = ((float4*)out)[r * 16 + ln];
        o.x += res.x; o.y += res.y; o.z += res.z; o.w += res.w;
        ((float4*)out)[r * 16 + ln] = o;
    }
}

extern "C" void kernel_launch(void* const* d_in, const int* in_sizes, int n_in,
                              void* d_out, int out_size) {
    const float* features = (const float*)d_in[0];
    const float* nb_W     = (const float*)d_in[1];
    const float* nb_b     = (const float*)d_in[2];
    const float* self_W   = (const float*)d_in[3];
    const float* self_b   = (const float*)d_in[4];
    const float* att1_W   = (const float*)d_in[5];
    const float* att1_b   = (const float*)d_in[6];
    const float* att2_W   = (const float*)d_in[7];
    const float* att2_b   = (const float*)d_in[8];
    const int*   row      = (const int*)d_in[9];
    const int*   col      = (const int*)d_in[10];
    float* out = (float*)d_out;

    float *g1, *g2, *xa, *xb, *mask, *dinv;
    int *rowptr, *wptr, *count, *ecol;
    cudaGetSymbolAddress((void**)&g1,     g_g1);
    cudaGetSymbolAddress((void**)&g2,     g_g2);
    cudaGetSymbolAddress((void**)&xa,     g_xa);
    cudaGetSymbolAddress((void**)&xb,     g_xb);
    cudaGetSymbolAddress((void**)&mask,   g_mask);
    cudaGetSymbolAddress((void**)&dinv,   g_dinv);
    cudaGetSymbolAddress((void**)&rowptr, g_rowptr);
    cudaGetSymbolAddress((void**)&wptr,   g_wptr);
    cudaGetSymbolAddress((void**)&count,  g_count);
    cudaGetSymbolAddress((void**)&ecol,   g_ecol);

    const int SMEM = 4 * 4096 * (int)sizeof(float);  // 64 KB weights
    cudaFuncSetAttribute(node_kernel,
                         cudaFuncAttributeMaxDynamicSharedMemorySize, SMEM);

    // out = features (x for layer 0 is read directly from features)
    cudaMemcpyAsync(out, features, (size_t)NN * 64 * sizeof(float),
                    cudaMemcpyDeviceToDevice);
    cudaMemsetAsync(count, 0, NN * sizeof(int));

    // ---- CSR build (once; reused by all 3 layers) ----
    hist_k<<<2048, 256>>>(row, count);       // kernel launch 0
    scan_k<<<1, 1024>>>(count, rowptr, wptr);// 1
    scatter_k<<<2048, 256>>>(row, col, wptr, ecol); // 2

    const float* xin[3]  = { features, xa, xb };
    float*       xout[3] = { xa, xb, xa };

    for (int l = 0; l < 3; l++) {
        node_kernel<<<3125, 256, SMEM>>>(    // l==0: launch 3
            xin[l],
            nb_W + l * 4096,   nb_b + l * 64,
            self_W + l * 4096, self_b + l * 64,
            att1_W + l * 8192, att1_b + l * 64,
            g1, g2);
        attn_k<<<12500, 256>>>(g1, g2, att2_W + l * 64, att2_b + l,
                               rowptr, ecol, mask, dinv);
        spmm_k<<<12500, 256>>>(xin[l], mask, dinv, rowptr, ecol,
                               xout[l], out);
    }
}

// round 7
// speedup vs baseline: 1.2460x; 1.0371x over previous
#include <cuda_runtime.h>
#include <math.h>

#define NN 100000
#define EE 1200000
#define F_GAMMA (-0.45f)
#define F_ZETA  (1.05f)

// ---------------- scratch (__device__ globals; no allocs allowed) ---------
__device__ float g_g1[NN * 64];
__device__ float g_g2[NN * 64];
__device__ float g_xa[NN * 64];
__device__ float g_xb[NN * 64];
__device__ float g_mask[EE];     // CSR order
__device__ float g_dinv[NN];
__device__ int   g_rowptr[NN + 1];
__device__ int   g_wptr[NN];
__device__ int   g_count[NN];
__device__ int   g_ecol[EE];     // CSR col indices

// ---------- init: out = features, count = 0 (kernel, for ncu indexing) ----
__global__ void init_k(const float* __restrict__ feat, float* __restrict__ out,
                       int* __restrict__ count) {
    int n4 = NN * 64 / 4;
    const float4* f4 = (const float4*)feat;
    float4* o4 = (float4*)out;
    for (int i = blockIdx.x * blockDim.x + threadIdx.x; i < n4;
         i += gridDim.x * blockDim.x) {
        o4[i] = f4[i];
        if (i < NN) count[i] = 0;
    }
}

// --------------------------- CSR build ------------------------------------
__global__ void hist_k(const int* __restrict__ row, int* __restrict__ count) {
    for (int e = blockIdx.x * blockDim.x + threadIdx.x; e < EE;
         e += gridDim.x * blockDim.x) atomicAdd(count + row[e], 1);
}

__global__ void __launch_bounds__(1024) scan_k(const int* __restrict__ count,
                                               int* __restrict__ rowptr,
                                               int* __restrict__ wptr) {
    __shared__ int s[1024];
    int t = threadIdx.x;
    const int CH = (NN + 1023) / 1024;
    int beg = t * CH;
    int end = beg + CH; if (end > NN) end = NN;
    int sum = 0;
    for (int i = beg; i < end; i++) sum += count[i];
    s[t] = sum;
    __syncthreads();
    for (int o = 1; o < 1024; o <<= 1) {
        int v = s[t];
        if (t >= o) v += s[t - o];
        __syncthreads();
        s[t] = v;
        __syncthreads();
    }
    int run = (t == 0) ? 0 : s[t - 1];
    for (int i = beg; i < end; i++) {
        rowptr[i] = run;
        wptr[i]   = run;
        run += count[i];
    }
    if (t == 1023) rowptr[NN] = EE;
}

__global__ void scatter_k(const int* __restrict__ row, const int* __restrict__ col,
                          int* __restrict__ wptr, int* __restrict__ ecol) {
    for (int e = blockIdx.x * blockDim.x + threadIdx.x; e < EE;
         e += gridDim.x * blockDim.x) {
        int r = row[e];
        int p = atomicAdd(wptr + r, 1);
        ecol[p] = col[e];
    }
}

// --------- per-node MLPs: 8 nodes/warp, float2 LDS, phased 32KB smem ------
// Lane owns output features (2*lane, 2*lane+1).
__global__ void __launch_bounds__(256) node_kernel(
    const float* __restrict__ x,
    const float* __restrict__ nbW,  const float* __restrict__ nbb,
    const float* __restrict__ sfW,  const float* __restrict__ sfb,
    const float* __restrict__ a1W,  const float* __restrict__ a1b,
    float* __restrict__ g1, float* __restrict__ g2) {
    __shared__ float sA[4096];   // 16 KB
    __shared__ float sB[4096];   // 16 KB

    const unsigned FULL = 0xffffffffu;
    int tid  = threadIdx.x;
    int lane = tid & 31;
    int gwarp = (blockIdx.x * blockDim.x + tid) >> 5;
    int base = gwarp * 8;

    // ---- phase 1 weights: nbW, sfW ----
    {
        const float4* a4 = (const float4*)nbW;
        const float4* b4 = (const float4*)sfW;
        for (int i = tid; i < 1024; i += 256) {
            ((float4*)sA)[i] = a4[i];
            ((float4*)sB)[i] = b4[i];
        }
    }
    __syncthreads();

    const float2* x2 = (const float2*)x;
    float2 xr[8];
    int   nid[8];
    bool  ok[8];
#pragma unroll
    for (int m = 0; m < 8; m++) {
        nid[m] = base + m;
        ok[m] = (nid[m] < NN);
        xr[m] = ok[m] ? x2[nid[m] * 32 + lane] : make_float2(0.f, 0.f);
    }

    float f1x[8], f1y[8], f2x[8], f2y[8];
    {
        float2 bn = ((const float2*)nbb)[lane];
        float2 bs = ((const float2*)sfb)[lane];
#pragma unroll
        for (int m = 0; m < 8; m++) {
            f1x[m] = bn.x; f1y[m] = bn.y;
            f2x[m] = bs.x; f2y[m] = bs.y;
        }
    }
    const float2* sA2 = (const float2*)sA;
    const float2* sB2 = (const float2*)sB;
#pragma unroll 4
    for (int k = 0; k < 64; k++) {
        float2 wn = sA2[k * 32 + lane];
        float2 ws = sB2[k * 32 + lane];
#pragma unroll
        for (int m = 0; m < 8; m++) {
            float xv = __shfl_sync(FULL, (k & 1) ? xr[m].y : xr[m].x, k >> 1);
            f1x[m] += xv * wn.x; f1y[m] += xv * wn.y;
            f2x[m] += xv * ws.x; f2y[m] += xv * ws.y;
        }
    }
#pragma unroll
    for (int m = 0; m < 8; m++) {
        f1x[m] = fmaxf(f1x[m], 0.f); f1y[m] = fmaxf(f1y[m], 0.f);
        f2x[m] = fmaxf(f2x[m], 0.f); f2y[m] = fmaxf(f2y[m], 0.f);
    }

    // ---- phase 2 weights: att1_W top/bot into the SAME smem ----
    __syncthreads();
    {
        const float4* t4 = (const float4*)a1W;
        const float4* b4 = (const float4*)(a1W + 4096);
        for (int i = tid; i < 1024; i += 256) {
            ((float4*)sA)[i] = t4[i];
            ((float4*)sB)[i] = b4[i];
        }
    }
    __syncthreads();

    float g1x[8], g1y[8], g2x[8], g2y[8];
    {
        float2 ab = ((const float2*)a1b)[lane];
#pragma unroll
        for (int m = 0; m < 8; m++) {
            g1x[m] = 0.f; g1y[m] = 0.f;
            g2x[m] = ab.x; g2y[m] = ab.y;
        }
    }
#pragma unroll 4
    for (int k = 0; k < 64; k++) {
        float2 wt = sA2[k * 32 + lane];
        float2 wb = sB2[k * 32 + lane];
#pragma unroll
        for (int m = 0; m < 8; m++) {
            float u = __shfl_sync(FULL, (k & 1) ? f1y[m] : f1x[m], k >> 1);
            float v = __shfl_sync(FULL, (k & 1) ? f2y[m] : f2x[m], k >> 1);
            g1x[m] += u * wt.x; g1y[m] += u * wt.y;
            g2x[m] += v * wb.x; g2y[m] += v * wb.y;
        }
    }

#pragma unroll
    for (int m = 0; m < 8; m++) {
        if (!ok[m]) continue;
        ((float2*)g1)[nid[m] * 32 + lane] = make_float2(g1x[m], g1y[m]);
        ((float2*)g2)[nid[m] * 32 + lane] = make_float2(g2x[m], g2y[m]);
    }
}

// ---- attention, CSR warp-per-row, 2 edges/iter via half-warps (float4) ---
__global__ void __launch_bounds__(256) attn_k(
    const float* __restrict__ g1, const float* __restrict__ g2,
    const float* __restrict__ a2W, const float* __restrict__ a2b,
    const int* __restrict__ rowptr, const int* __restrict__ ecol,
    float* __restrict__ mask, float* __restrict__ dinv) {
    int lane = threadIdx.x & 31;
    int half = lane >> 4;
    int ln   = lane & 15;
    unsigned hm = 0xFFFFu << (half << 4);
    int r = (blockIdx.x * blockDim.x + threadIdx.x) >> 5;
    if (r >= NN) return;

    float4 w = ((const float4*)a2W)[ln];
    float bias = a2b[0];
    float4 a = ((const float4*)g1)[r * 16 + ln];
    const float4* g2v = (const float4*)g2;

    int p0 = __ldg(rowptr + r), p1 = __ldg(rowptr + r + 1);
    float rs = 0.f;
#pragma unroll 4
    for (int p = p0 + half; p < p1; p += 2) {
        int c = __ldg(ecol + p);
        float4 b = g2v[c * 16 + ln];
        float s = fmaxf(a.x + b.x, 0.f) * w.x
                + fmaxf(a.y + b.y, 0.f) * w.y
                + fmaxf(a.z + b.z, 0.f) * w.z
                + fmaxf(a.w + b.w, 0.f) * w.w;
        s += __shfl_xor_sync(hm, s, 8);
        s += __shfl_xor_sync(hm, s, 4);
        s += __shfl_xor_sync(hm, s, 2);
        s += __shfl_xor_sync(hm, s, 1);
        float sig = 1.f / (1.f + __expf(-(s + bias)));
        float mk  = fminf(fmaxf(sig * (F_ZETA - F_GAMMA) + F_GAMMA, 0.f), 1.f);
        if (ln == 0) mask[p] = mk;
        rs += mk;
    }
    rs += __shfl_xor_sync(0xffffffffu, rs, 16);
    if (lane == 0) dinv[r] = fminf(rsqrtf(rs + 1e-6f), 10.f);
}

// -- SpMM CSR warp-per-row, 2 edges/iter via half-warps, fused epilogue ----
__global__ void __launch_bounds__(256) spmm_k(
    const float* __restrict__ x, const float* __restrict__ mask,
    const float* __restrict__ dinv,
    const int* __restrict__ rowptr, const int* __restrict__ ecol,
    float* __restrict__ xnew, float* __restrict__ out) {
    const unsigned FULL = 0xffffffffu;
    int lane = threadIdx.x & 31;
    int half = lane >> 4;
    int ln   = lane & 15;
    int r = (blockIdx.x * blockDim.x + threadIdx.x) >> 5;
    if (r >= NN) return;

    const float4* x4 = (const float4*)x;
    int p0 = __ldg(rowptr + r), p1 = __ldg(rowptr + r + 1);
    float ax = 0.f, ay = 0.f, az = 0.f, aw = 0.f;
#pragma unroll 4
    for (int p = p0 + half; p < p1; p += 2) {
        int c = __ldg(ecol + p);
        float v = __ldg(mask + p) * __ldg(dinv + c);
        float4 xv = x4[c * 16 + ln];
        ax += v * xv.x; ay += v * xv.y; az += v * xv.z; aw += v * xv.w;
    }
    ax += __shfl_xor_sync(FULL, ax, 16);
    ay += __shfl_xor_sync(FULL, ay, 16);
    az += __shfl_xor_sync(FULL, az, 16);
    aw += __shfl_xor_sync(FULL, aw, 16);
    if (half == 0) {
        float dr = __ldg(dinv + r);
        float4 res = make_float4(ax * dr, ay * dr, az * dr, aw * dr);
        ((float4*)xnew)[r * 16 + ln] = res;
        float4 o = ((float4*)out)[r * 16 + ln];
        o.x += res.x; o.y += res.y; o.z += res.z; o.w += res.w;
        ((float4*)out)[r * 16 + ln] = o;
    }
}

extern "C" void kernel_launch(void* const* d_in, const int* in_sizes, int n_in,
                              void* d_out, int out_size) {
    const float* features = (const float*)d_in[0];
    const float* nb_W     = (const float*)d_in[1];
    const float* nb_b     = (const float*)d_in[2];
    const float* self_W   = (const float*)d_in[3];
    const float* self_b   = (const float*)d_in[4];
    const float* att1_W   = (const float*)d_in[5];
    const float* att1_b   = (const float*)d_in[6];
    const float* att2_W   = (const float*)d_in[7];
    const float* att2_b   = (const float*)d_in[8];
    const int*   row      = (const int*)d_in[9];
    const int*   col      = (const int*)d_in[10];
    float* out = (float*)d_out;

    float *g1, *g2, *xa, *xb, *mask, *dinv;
    int *rowptr, *wptr, *count, *ecol;
    cudaGetSymbolAddress((void**)&g1,     g_g1);
    cudaGetSymbolAddress((void**)&g2,     g_g2);
    cudaGetSymbolAddress((void**)&xa,     g_xa);
    cudaGetSymbolAddress((void**)&xb,     g_xb);
    cudaGetSymbolAddress((void**)&mask,   g_mask);
    cudaGetSymbolAddress((void**)&dinv,   g_dinv);
    cudaGetSymbolAddress((void**)&rowptr, g_rowptr);
    cudaGetSymbolAddress((void**)&wptr,   g_wptr);
    cudaGetSymbolAddress((void**)&count,  g_count);
    cudaGetSymbolAddress((void**)&ecol,   g_ecol);

    // launch index:                                  0
    init_k<<<2048, 256>>>(features, out, count);
    // ---- CSR build (once; reused by all 3 layers) 1,2,3 ----
    hist_k<<<2048, 256>>>(row, count);
    scan_k<<<1, 1024>>>(count, rowptr, wptr);
    scatter_k<<<2048, 256>>>(row, col, wptr, ecol);

    const float* xin[3]  = { features, xa, xb };
    float*       xout[3] = { xa, xb, xa };

    for (int l = 0; l < 3; l++) {
        node_kernel<<<1563, 256>>>(          // l==0: launch 4
            xin[l],
            nb_W + l * 4096,   nb_b + l * 64,
            self_W + l * 4096, self_b + l * 64,
            att1_W + l * 8192, att1_b + l * 64,
            g1, g2);
        attn_k<<<12500, 256>>>(g1, g2, att2_W + l * 64, att2_b + l,
                               rowptr, ecol, mask, dinv);   // l==0: launch 5 -> profiled
        spmm_k<<<12500, 256>>>(xin[l], mask, dinv, rowptr, ecol,
                               xout[l], out);
    }
}

// round 10
// speedup vs baseline: 1.2651x; 1.0154x over previous
#include <cuda_runtime.h>
#include <cuda_fp16.h>
#include <math.h>

#define NN 100000
#define EE 1200000
#define F_GAMMA (-0.45f)
#define F_ZETA  (1.05f)

// ---------------- scratch (__device__ globals; no allocs allowed) ---------
__device__ __half g_g1[NN * 64];   // fp16 attention operands
__device__ __half g_g2[NN * 64];
__device__ float  g_xa[NN * 64];
__device__ float  g_xb[NN * 64];
__device__ float  g_mask[EE];      // CSR order
__device__ float  g_dinv[NN];
__device__ int    g_rowptr[NN + 1];
__device__ int    g_wptr[NN];
__device__ int    g_count[NN];
__device__ int    g_ecol[EE];      // CSR col indices

// --------------------------- CSR build ------------------------------------
__global__ void __launch_bounds__(1024) scan_k(const int* __restrict__ count,
                                               int* __restrict__ rowptr,
                                               int* __restrict__ wptr) {
    __shared__ int s[1024];
    int t = threadIdx.x;
    const int CH = (NN + 1023) / 1024;
    int beg = t * CH;
    int end = beg + CH; if (end > NN) end = NN;
    int sum = 0;
    for (int i = beg; i < end; i++) sum += count[i];
    s[t] = sum;
    __syncthreads();
    for (int o = 1; o < 1024; o <<= 1) {
        int v = s[t];
        if (t >= o) v += s[t - o];
        __syncthreads();
        s[t] = v;
        __syncthreads();
    }
    int run = (t == 0) ? 0 : s[t - 1];
    for (int i = beg; i < end; i++) {
        rowptr[i] = run;
        wptr[i]   = run;
        run += count[i];
    }
    if (t == 1023) rowptr[NN] = EE;
}

__global__ void scatter_k(const int* __restrict__ row, const int* __restrict__ col,
                          int* __restrict__ wptr, int* __restrict__ ecol) {
    for (int e = blockIdx.x * blockDim.x + threadIdx.x; e < EE;
         e += gridDim.x * blockDim.x) {
        int r = row[e];
        int p = atomicAdd(wptr + r, 1);
        ecol[p] = col[e];
    }
}

// --------- per-node MLPs: 8 nodes/warp, float2 LDS, phased 32KB smem ------
// Lane owns output features (2*lane, 2*lane+1); g1/g2 stored as half2.
// Layer 0 additionally builds the row histogram (fused to save a launch and
// keep attn_k at profiled launch index 3).
__global__ void __launch_bounds__(256) node_kernel(
    const float* __restrict__ x,
    const float* __restrict__ nbW,  const float* __restrict__ nbb,
    const float* __restrict__ sfW,  const float* __restrict__ sfb,
    const float* __restrict__ a1W,  const float* __restrict__ a1b,
    __half* __restrict__ g1, __half* __restrict__ g2,
    const int* __restrict__ row, int* __restrict__ count, int do_hist) {
    __shared__ float sA[4096];   // 16 KB
    __shared__ float sB[4096];   // 16 KB

    const unsigned FULL = 0xffffffffu;
    int tid  = threadIdx.x;
    int lane = tid & 31;
    int gtid = blockIdx.x * blockDim.x + tid;
    int gwarp = gtid >> 5;
    int base = gwarp * 8;

    // ---- fused histogram (layer 0 only) ----
    if (do_hist) {
        int stride = gridDim.x * blockDim.x;
        for (int e = gtid; e < EE; e += stride)
            atomicAdd(count + __ldg(row + e), 1);
    }

    // ---- phase 1 weights: nbW, sfW ----
    {
        const float4* a4 = (const float4*)nbW;
        const float4* b4 = (const float4*)sfW;
        for (int i = tid; i < 1024; i += 256) {
            ((float4*)sA)[i] = a4[i];
            ((float4*)sB)[i] = b4[i];
        }
    }
    __syncthreads();

    const float2* x2 = (const float2*)x;
    float2 xr[8];
    int   nid[8];
    bool  ok[8];
#pragma unroll
    for (int m = 0; m < 8; m++) {
        nid[m] = base + m;
        ok[m] = (nid[m] < NN);
        xr[m] = ok[m] ? x2[nid[m] * 32 + lane] : make_float2(0.f, 0.f);
    }

    float f1x[8], f1y[8], f2x[8], f2y[8];
    {
        float2 bn = ((const float2*)nbb)[lane];
        float2 bs = ((const float2*)sfb)[lane];
#pragma unroll
        for (int m = 0; m < 8; m++) {
            f1x[m] = bn.x; f1y[m] = bn.y;
            f2x[m] = bs.x; f2y[m] = bs.y;
        }
    }
    const float2* sA2 = (const float2*)sA;
    const float2* sB2 = (const float2*)sB;
#pragma unroll 4
    for (int k = 0; k < 64; k++) {
        float2 wn = sA2[k * 32 + lane];
        float2 ws = sB2[k * 32 + lane];
#pragma unroll
        for (int m = 0; m < 8; m++) {
            float xv = __shfl_sync(FULL, (k & 1) ? xr[m].y : xr[m].x, k >> 1);
            f1x[m] += xv * wn.x; f1y[m] += xv * wn.y;
            f2x[m] += xv * ws.x; f2y[m] += xv * ws.y;
        }
    }
#pragma unroll
    for (int m = 0; m < 8; m++) {
        f1x[m] = fmaxf(f1x[m], 0.f); f1y[m] = fmaxf(f1y[m], 0.f);
        f2x[m] = fmaxf(f2x[m], 0.f); f2y[m] = fmaxf(f2y[m], 0.f);
    }

    // ---- phase 2 weights: att1_W top/bot into the SAME smem ----
    __syncthreads();
    {
        const float4* t4 = (const float4*)a1W;
        const float4* b4 = (const float4*)(a1W + 4096);
        for (int i = tid; i < 1024; i += 256) {
            ((float4*)sA)[i] = t4[i];
            ((float4*)sB)[i] = b4[i];
        }
    }
    __syncthreads();

    float g1x[8], g1y[8], g2x[8], g2y[8];
    {
        float2 ab = ((const float2*)a1b)[lane];
#pragma unroll
        for (int m = 0; m < 8; m++) {
            g1x[m] = 0.f; g1y[m] = 0.f;
            g2x[m] = ab.x; g2y[m] = ab.y;
        }
    }
#pragma unroll 4
    for (int k = 0; k < 64; k++) {
        float2 wt = sA2[k * 32 + lane];
        float2 wb = sB2[k * 32 + lane];
#pragma unroll
        for (int m = 0; m < 8; m++) {
            float u = __shfl_sync(FULL, (k & 1) ? f1y[m] : f1x[m], k >> 1);
            float v = __shfl_sync(FULL, (k & 1) ? f2y[m] : f2x[m], k >> 1);
            g1x[m] += u * wt.x; g1y[m] += u * wt.y;
            g2x[m] += v * wb.x; g2y[m] += v * wb.y;
        }
    }

#pragma unroll
    for (int m = 0; m < 8; m++) {
        if (!ok[m]) continue;
        ((__half2*)g1)[nid[m] * 32 + lane] = __floats2half2_rn(g1x[m], g1y[m]);
        ((__half2*)g2)[nid[m] * 32 + lane] = __floats2half2_rn(g2x[m], g2y[m]);
    }
}

// ---- attention: CSR warp-per-row, 2 edges/iter, fp16 gathers (128B/edge) -
__global__ void __launch_bounds__(256) attn_k(
    const __half* __restrict__ g1, const __half* __restrict__ g2,
    const float* __restrict__ a2W, const float* __restrict__ a2b,
    const int* __restrict__ rowptr, const int* __restrict__ ecol,
    float* __restrict__ mask, float* __restrict__ dinv) {
    int lane = threadIdx.x & 31;
    int half = lane >> 4;
    int ln   = lane & 15;
    unsigned hm = 0xFFFFu << (half << 4);
    int r = (blockIdx.x * blockDim.x + threadIdx.x) >> 5;
    if (r >= NN) return;

    float4 w = ((const float4*)a2W)[ln];
    float bias = a2b[0];
    // lane ln owns features 4*ln .. 4*ln+3 (two half2s = uint2)
    const uint2* g1v = (const uint2*)g1;
    const uint2* g2v = (const uint2*)g2;
    uint2 ar = g1v[r * 16 + ln];
    float2 a01 = __half22float2(*(const __half2*)&ar.x);
    float2 a23 = __half22float2(*(const __half2*)&ar.y);

    int p0 = __ldg(rowptr + r), p1 = __ldg(rowptr + r + 1);
    float rs = 0.f;
#pragma unroll 4
    for (int p = p0 + half; p < p1; p += 2) {
        int c = __ldg(ecol + p);
        uint2 br = g2v[c * 16 + ln];
        float2 b01 = __half22float2(*(const __half2*)&br.x);
        float2 b23 = __half22float2(*(const __half2*)&br.y);
        float s = fmaxf(a01.x + b01.x, 0.f) * w.x
                + fmaxf(a01.y + b01.y, 0.f) * w.y
                + fmaxf(a23.x + b23.x, 0.f) * w.z
                + fmaxf(a23.y + b23.y, 0.f) * w.w;
        s += __shfl_xor_sync(hm, s, 8);
        s += __shfl_xor_sync(hm, s, 4);
        s += __shfl_xor_sync(hm, s, 2);
        s += __shfl_xor_sync(hm, s, 1);
        float sig = 1.f / (1.f + __expf(-(s + bias)));
        float mk  = fminf(fmaxf(sig * (F_ZETA - F_GAMMA) + F_GAMMA, 0.f), 1.f);
        if (ln == 0) mask[p] = mk;
        rs += mk;
    }
    rs += __shfl_xor_sync(0xffffffffu, rs, 16);
    if (lane == 0) dinv[r] = fminf(rsqrtf(rs + 1e-6f), 10.f);
}

// -- SpMM CSR warp-per-row, 2 edges/iter via half-warps, fused epilogue ----
// out[r] = base[r] + xnew[r]; base = features (layer 0) or out (layers 1,2).
__global__ void __launch_bounds__(256) spmm_k(
    const float* __restrict__ x, const float* __restrict__ mask,
    const float* __restrict__ dinv,
    const int* __restrict__ rowptr, const int* __restrict__ ecol,
    float* __restrict__ xnew, const float* __restrict__ base,
    float* __restrict__ out) {
    const unsigned FULL = 0xffffffffu;
    int lane = threadIdx.x & 31;
    int half = lane >> 4;
    int ln   = lane & 15;
    int r = (blockIdx.x * blockDim.x + threadIdx.x) >> 5;
    if (r >= NN) return;

    const float4* x4 = (const float4*)x;
    int p0 = __ldg(rowptr + r), p1 = __ldg(rowptr + r + 1);
    float ax = 0.f, ay = 0.f, az = 0.f, aw = 0.f;
#pragma unroll 4
    for (int p = p0 + half; p < p1; p += 2) {
        int c = __ldg(ecol + p);
        float v = __ldg(mask + p) * __ldg(dinv + c);
        float4 xv = x4[c * 16 + ln];
        ax += v * xv.x; ay += v * xv.y; az += v * xv.z; aw += v * xv.w;
    }
    ax += __shfl_xor_sync(FULL, ax, 16);
    ay += __shfl_xor_sync(FULL, ay, 16);
    az += __shfl_xor_sync(FULL, az, 16);
    aw += __shfl_xor_sync(FULL, aw, 16);
    if (half == 0) {
        float dr = __ldg(dinv + r);
        float4 res = make_float4(ax * dr, ay * dr, az * dr, aw * dr);
        ((float4*)xnew)[r * 16 + ln] = res;
        float4 b = ((const float4*)base)[r * 16 + ln];
        b.x += res.x; b.y += res.y; b.z += res.z; b.w += res.w;
        ((float4*)out)[r * 16 + ln] = b;
    }
}

extern "C" void kernel_launch(void* const* d_in, const int* in_sizes, int n_in,
                              void* d_out, int out_size) {
    const float* features = (const float*)d_in[0];
    const float* nb_W     = (const float*)d_in[1];
    const float* nb_b     = (const float*)d_in[2];
    const float* self_W   = (const float*)d_in[3];
    const float* self_b   = (const float*)d_in[4];
    const float* att1_W   = (const float*)d_in[5];
    const float* att1_b   = (const float*)d_in[6];
    const float* att2_W   = (const float*)d_in[7];
    const float* att2_b   = (const float*)d_in[8];
    const int*   row      = (const int*)d_in[9];
    const int*   col      = (const int*)d_in[10];
    float* out = (float*)d_out;

    __half *g1, *g2;
    float *xa, *xb, *mask, *dinv;
    int *rowptr, *wptr, *count, *ecol;
    cudaGetSymbolAddress((void**)&g1,     g_g1);
    cudaGetSymbolAddress((void**)&g2,     g_g2);
    cudaGetSymbolAddress((void**)&xa,     g_xa);
    cudaGetSymbolAddress((void**)&xb,     g_xb);
    cudaGetSymbolAddress((void**)&mask,   g_mask);
    cudaGetSymbolAddress((void**)&dinv,   g_dinv);
    cudaGetSymbolAddress((void**)&rowptr, g_rowptr);
    cudaGetSymbolAddress((void**)&wptr,   g_wptr);
    cudaGetSymbolAddress((void**)&count,  g_count);
    cudaGetSymbolAddress((void**)&ecol,   g_ecol);

    cudaMemsetAsync(count, 0, NN * sizeof(int));   // not a kernel launch

    const float* xin[3]  = { features, xa, xb };
    float*       xout[3] = { xa, xb, xa };

    // kernel 0: node l0 (+ fused histogram)
    node_kernel<<<1563, 256>>>(features,
        nb_W, nb_b, self_W, self_b, att1_W, att1_b,
        g1, g2, row, count, 1);
    // kernels 1,2: finish CSR
    scan_k<<<1, 1024>>>(count, rowptr, wptr);
    scatter_k<<<2048, 256>>>(row, col, wptr, ecol);

    for (int l = 0; l < 3; l++) {
        if (l > 0) {
            node_kernel<<<1563, 256>>>(xin[l],
                nb_W + l * 4096,   nb_b + l * 64,
                self_W + l * 4096, self_b + l * 64,
                att1_W + l * 8192, att1_b + l * 64,
                g1, g2, row, count, 0);
        }
        // l==0: kernel index 3 -> profiled
        attn_k<<<12500, 256>>>(g1, g2, att2_W + l * 64, att2_b + l,
                               rowptr, ecol, mask, dinv);
        spmm_k<<<12500, 256>>>(xin[l], mask, dinv, rowptr, ecol,
                               xout[l], (l == 0) ? features : out, out);
    }
}

// round 12
// speedup vs baseline: 1.3596x; 1.0747x over previous
#include <cuda_runtime.h>
#include <cuda_fp16.h>
#include <math.h>

#define NN 100000
#define EE 1200000
#define F_GAMMA (-0.45f)
#define F_ZETA  (1.05f)

typedef unsigned long long ull;

// packed f32x2 helpers (Blackwell: fma.rn.f32x2 is PTX-only, ptxas won't fuse)
#define PACKF2(d, x, y) \
    asm("mov.b64 %0, {%1,%2};" : "=l"(d) \
        : "r"(__float_as_uint(x)), "r"(__float_as_uint(y)))
#define UNPACKF2(x, y, d) do { unsigned _lo, _hi; \
    asm("mov.b64 {%0,%1}, %2;" : "=r"(_lo), "=r"(_hi) : "l"(d)); \
    (x) = __uint_as_float(_lo); (y) = __uint_as_float(_hi); } while (0)
#define FMAF2(d, a, b, c) \
    asm("fma.rn.f32x2 %0, %1, %2, %3;" : "=l"(d) : "l"(a), "l"(b), "l"(c))

// ---------------- scratch (__device__ globals; no allocs allowed) ---------
__device__ __half g_g1[NN * 64];   // fp16 attention operands
__device__ __half g_g2[NN * 64];
__device__ float  g_xa[NN * 64];
__device__ float  g_xb[NN * 64];
__device__ float  g_mask[EE];      // CSR order
__device__ float  g_dinv[NN];
__device__ int    g_rowptr[NN + 1];
__device__ int    g_wptr[NN];
__device__ int    g_count[NN];
__device__ int    g_ecol[EE];      // CSR col indices

// --------------------------- CSR build ------------------------------------
__global__ void __launch_bounds__(1024) scan_k(const int* __restrict__ count,
                                               int* __restrict__ rowptr,
                                               int* __restrict__ wptr) {
    __shared__ int s[1024];
    int t = threadIdx.x;
    const int CH = (NN + 1023) / 1024;
    int beg = t * CH;
    int end = beg + CH; if (end > NN) end = NN;
    int sum = 0;
    for (int i = beg; i < end; i++) sum += count[i];
    s[t] = sum;
    __syncthreads();
    for (int o = 1; o < 1024; o <<= 1) {
        int v = s[t];
        if (t >= o) v += s[t - o];
        __syncthreads();
        s[t] = v;
        __syncthreads();
    }
    int run = (t == 0) ? 0 : s[t - 1];
    for (int i = beg; i < end; i++) {
        rowptr[i] = run;
        wptr[i]   = run;
        run += count[i];
    }
    if (t == 1023) rowptr[NN] = EE;
}

__global__ void scatter_k(const int* __restrict__ row, const int* __restrict__ col,
                          int* __restrict__ wptr, int* __restrict__ ecol) {
    for (int e = blockIdx.x * blockDim.x + threadIdx.x; e < EE;
         e += gridDim.x * blockDim.x) {
        int r = row[e];
        int p = atomicAdd(wptr + r, 1);
        ecol[p] = col[e];
    }
}

// --------- per-node MLPs: 8 nodes/warp, FFMA2 phase1, phased 32KB smem ----
__global__ void __launch_bounds__(256) node_kernel(
    const float* __restrict__ x,
    const float* __restrict__ nbW,  const float* __restrict__ nbb,
    const float* __restrict__ sfW,  const float* __restrict__ sfb,
    const float* __restrict__ a1W,  const float* __restrict__ a1b,
    __half* __restrict__ g1, __half* __restrict__ g2,
    const int* __restrict__ row, int* __restrict__ count, int do_hist) {
    __shared__ float sA[4096];   // 16 KB
    __shared__ float sB[4096];   // 16 KB

    const unsigned FULL = 0xffffffffu;
    int tid  = threadIdx.x;
    int lane = tid & 31;
    int gtid = blockIdx.x * blockDim.x + tid;
    int gwarp = gtid >> 5;
    int base = gwarp * 8;

    // ---- fused histogram (layer 0 only) ----
    if (do_hist) {
        int stride = gridDim.x * blockDim.x;
        for (int e = gtid; e < EE; e += stride)
            atomicAdd(count + __ldg(row + e), 1);
    }

    // ---- phase 1 weights: nbW, sfW ----
    {
        const float4* a4 = (const float4*)nbW;
        const float4* b4 = (const float4*)sfW;
        for (int i = tid; i < 1024; i += 256) {
            ((float4*)sA)[i] = a4[i];
            ((float4*)sB)[i] = b4[i];
        }
    }
    __syncthreads();

    const float2* x2 = (const float2*)x;
    float2 xr[8];
    int   nid[8];
    bool  ok[8];
#pragma unroll
    for (int m = 0; m < 8; m++) {
        nid[m] = base + m;
        ok[m] = (nid[m] < NN);
        xr[m] = ok[m] ? x2[nid[m] * 32 + lane] : make_float2(0.f, 0.f);
    }

    // packed accumulators: f1[m] = (f1x, f1y), f2[m] = (f2x, f2y)
    ull f1[8], f2[8];
    {
        float2 bn = ((const float2*)nbb)[lane];
        float2 bs = ((const float2*)sfb)[lane];
#pragma unroll
        for (int m = 0; m < 8; m++) {
            PACKF2(f1[m], bn.x, bn.y);
            PACKF2(f2[m], bs.x, bs.y);
        }
    }
    const float2* sA2 = (const float2*)sA;
    const float2* sB2 = (const float2*)sB;
#pragma unroll 4
    for (int k = 0; k < 64; k++) {
        float2 wn = sA2[k * 32 + lane];
        float2 ws = sB2[k * 32 + lane];
        ull wn2, ws2;
        PACKF2(wn2, wn.x, wn.y);
        PACKF2(ws2, ws.x, ws.y);
#pragma unroll
        for (int m = 0; m < 8; m++) {
            float xv = __shfl_sync(FULL, (k & 1) ? xr[m].y : xr[m].x, k >> 1);
            ull xv2;
            PACKF2(xv2, xv, xv);
            FMAF2(f1[m], xv2, wn2, f1[m]);
            FMAF2(f2[m], xv2, ws2, f2[m]);
        }
    }
    float f1x[8], f1y[8], f2x[8], f2y[8];
#pragma unroll
    for (int m = 0; m < 8; m++) {
        UNPACKF2(f1x[m], f1y[m], f1[m]);
        UNPACKF2(f2x[m], f2y[m], f2[m]);
        f1x[m] = fmaxf(f1x[m], 0.f); f1y[m] = fmaxf(f1y[m], 0.f);
        f2x[m] = fmaxf(f2x[m], 0.f); f2y[m] = fmaxf(f2y[m], 0.f);
    }

    // ---- phase 2 weights: att1_W top/bot into the SAME smem ----
    __syncthreads();
    {
        const float4* t4 = (const float4*)a1W;
        const float4* b4 = (const float4*)(a1W + 4096);
        for (int i = tid; i < 1024; i += 256) {
            ((float4*)sA)[i] = t4[i];
            ((float4*)sB)[i] = b4[i];
        }
    }
    __syncthreads();

    float g1x[8], g1y[8], g2x[8], g2y[8];
    {
        float2 ab = ((const float2*)a1b)[lane];
#pragma unroll
        for (int m = 0; m < 8; m++) {
            g1x[m] = 0.f; g1y[m] = 0.f;
            g2x[m] = ab.x; g2y[m] = ab.y;
        }
    }
#pragma unroll 4
    for (int k = 0; k < 64; k++) {
        float2 wt = sA2[k * 32 + lane];
        float2 wb = sB2[k * 32 + lane];
#pragma unroll
        for (int m = 0; m < 8; m++) {
            float u = __shfl_sync(FULL, (k & 1) ? f1y[m] : f1x[m], k >> 1);
            float v = __shfl_sync(FULL, (k & 1) ? f2y[m] : f2x[m], k >> 1);
            g1x[m] += u * wt.x; g1y[m] += u * wt.y;
            g2x[m] += v * wb.x; g2y[m] += v * wb.y;
        }
    }

#pragma unroll
    for (int m = 0; m < 8; m++) {
        if (!ok[m]) continue;
        ((__half2*)g1)[nid[m] * 32 + lane] = __floats2half2_rn(g1x[m], g1y[m]);
        ((__half2*)g2)[nid[m] * 32 + lane] = __floats2half2_rn(g2x[m], g2y[m]);
    }
}

// ---- attention: CSR warp-per-row, 2 edges/iter, half2 math throughout ----
__global__ void __launch_bounds__(256) attn_k(
    const __half* __restrict__ g1, const __half* __restrict__ g2,
    const float* __restrict__ a2W, const float* __restrict__ a2b,
    const int* __restrict__ rowptr, const int* __restrict__ ecol,
    float* __restrict__ mask, float* __restrict__ dinv) {
    int lane = threadIdx.x & 31;
    int half = lane >> 4;
    int ln   = lane & 15;
    unsigned hm = 0xFFFFu << (half << 4);
    int r = (blockIdx.x * blockDim.x + threadIdx.x) >> 5;
    if (r >= NN) return;

    float4 w = ((const float4*)a2W)[ln];
    __half2 w01 = __floats2half2_rn(w.x, w.y);
    __half2 w23 = __floats2half2_rn(w.z, w.w);
    __half2 hz  = __float2half2_rn(0.f);
    float bias = a2b[0];

    const uint2* g1v = (const uint2*)g1;
    const uint2* g2v = (const uint2*)g2;
    uint2 ar = g1v[r * 16 + ln];
    __half2 a0 = *(const __half2*)&ar.x;
    __half2 a1 = *(const __half2*)&ar.y;

    int p0 = __ldg(rowptr + r), p1 = __ldg(rowptr + r + 1);
    float rs = 0.f;
#pragma unroll 4
    for (int p = p0 + half; p < p1; p += 2) {
        int c = __ldg(ecol + p);
        uint2 br = g2v[c * 16 + ln];
        __half2 t0 = __hmax2(__hadd2(a0, *(const __half2*)&br.x), hz);
        __half2 t1 = __hmax2(__hadd2(a1, *(const __half2*)&br.y), hz);
        __half2 acc = __hfma2(t0, w01, __hmul2(t1, w23));
        float s = __low2float(acc) + __high2float(acc);
        s += __shfl_xor_sync(hm, s, 8);
        s += __shfl_xor_sync(hm, s, 4);
        s += __shfl_xor_sync(hm, s, 2);
        s += __shfl_xor_sync(hm, s, 1);
        float sig = __fdividef(1.f, 1.f + __expf(-(s + bias)));
        float mk  = fminf(fmaxf(sig * (F_ZETA - F_GAMMA) + F_GAMMA, 0.f), 1.f);
        if (ln == 0) mask[p] = mk;
        rs += mk;
    }
    rs += __shfl_xor_sync(0xffffffffu, rs, 16);
    if (lane == 0) dinv[r] = fminf(rsqrtf(rs + 1e-6f), 10.f);
}

// -- SpMM CSR warp-per-row, 2 edges/iter, f32x2 accumulate, fused epilogue -
__global__ void __launch_bounds__(256) spmm_k(
    const float* __restrict__ x, const float* __restrict__ mask,
    const float* __restrict__ dinv,
    const int* __restrict__ rowptr, const int* __restrict__ ecol,
    float* __restrict__ xnew, const float* __restrict__ base,
    float* __restrict__ out) {
    const unsigned FULL = 0xffffffffu;
    int lane = threadIdx.x & 31;
    int half = lane >> 4;
    int ln   = lane & 15;
    int r = (blockIdx.x * blockDim.x + threadIdx.x) >> 5;
    if (r >= NN) return;

    const ulonglong2* x16 = (const ulonglong2*)x;
    int p0 = __ldg(rowptr + r), p1 = __ldg(rowptr + r + 1);
    ull a01 = 0ull, a23 = 0ull;   // (0.f,0.f) bit pattern
#pragma unroll 4
    for (int p = p0 + half; p < p1; p += 2) {
        int c = __ldg(ecol + p);
        float v = __ldg(mask + p) * __ldg(dinv + c);
        ull v2;
        PACKF2(v2, v, v);
        ulonglong2 xv = x16[c * 16 + ln];
        FMAF2(a01, v2, xv.x, a01);
        FMAF2(a23, v2, xv.y, a23);
    }
    float ax, ay, az, aw;
    UNPACKF2(ax, ay, a01);
    UNPACKF2(az, aw, a23);
    ax += __shfl_xor_sync(FULL, ax, 16);
    ay += __shfl_xor_sync(FULL, ay, 16);
    az += __shfl_xor_sync(FULL, az, 16);
    aw += __shfl_xor_sync(FULL, aw, 16);
    if (half == 0) {
        float dr = __ldg(dinv + r);
        float4 res = make_float4(ax * dr, ay * dr, az * dr, aw * dr);
        ((float4*)xnew)[r * 16 + ln] = res;
        float4 b = ((const float4*)base)[r * 16 + ln];
        b.x += res.x; b.y += res.y; b.z += res.z; b.w += res.w;
        ((float4*)out)[r * 16 + ln] = b;
    }
}

extern "C" void kernel_launch(void* const* d_in, const int* in_sizes, int n_in,
                              void* d_out, int out_size) {
    const float* features = (const float*)d_in[0];
    const float* nb_W     = (const float*)d_in[1];
    const float* nb_b     = (const float*)d_in[2];
    const float* self_W   = (const float*)d_in[3];
    const float* self_b   = (const float*)d_in[4];
    const float* att1_W   = (const float*)d_in[5];
    const float* att1_b   = (const float*)d_in[6];
    const float* att2_W   = (const float*)d_in[7];
    const float* att2_b   = (const float*)d_in[8];
    const int*   row      = (const int*)d_in[9];
    const int*   col      = (const int*)d_in[10];
    float* out = (float*)d_out;

    __half *g1, *g2;
    float *xa, *xb, *mask, *dinv;
    int *rowptr, *wptr, *count, *ecol;
    cudaGetSymbolAddress((void**)&g1,     g_g1);
    cudaGetSymbolAddress((void**)&g2,     g_g2);
    cudaGetSymbolAddress((void**)&xa,     g_xa);
    cudaGetSymbolAddress((void**)&xb,     g_xb);
    cudaGetSymbolAddress((void**)&mask,   g_mask);
    cudaGetSymbolAddress((void**)&dinv,   g_dinv);
    cudaGetSymbolAddress((void**)&rowptr, g_rowptr);
    cudaGetSymbolAddress((void**)&wptr,   g_wptr);
    cudaGetSymbolAddress((void**)&count,  g_count);
    cudaGetSymbolAddress((void**)&ecol,   g_ecol);

    cudaMemsetAsync(count, 0, NN * sizeof(int));   // not a kernel launch

    const float* xin[3]  = { features, xa, xb };
    float*       xout[3] = { xa, xb, xa };

    // kernel 0: node l0 (+ fused histogram)
    node_kernel<<<1563, 256>>>(features,
        nb_W, nb_b, self_W, self_b, att1_W, att1_b,
        g1, g2, row, count, 1);
    // kernels 1,2: finish CSR
    scan_k<<<1, 1024>>>(count, rowptr, wptr);
    scatter_k<<<2048, 256>>>(row, col, wptr, ecol);

    for (int l = 0; l < 3; l++) {
        if (l > 0) {
            node_kernel<<<1563, 256>>>(xin[l],
                nb_W + l * 4096,   nb_b + l * 64,
                self_W + l * 4096, self_b + l * 64,
                att1_W + l * 8192, att1_b + l * 64,
                g1, g2, row, count, 0);
        }
        // l==0: kernel index 3 -> profiled (verifies half2 attn rewrite)
        attn_k<<<12500, 256>>>(g1, g2, att2_W + l * 64, att2_b + l,
                               rowptr, ecol, mask, dinv);
        spmm_k<<<12500, 256>>>(xin[l], mask, dinv, rowptr, ecol,
                               xout[l], (l == 0) ? features : out, out);
    }
}

// round 16
// speedup vs baseline: 1.3615x; 1.0014x over previous
#include <cuda_runtime.h>
#include <cuda_fp16.h>
#include <math.h>

#define NN 100000
#define EE 1200000
#define F_GAMMA (-0.45f)
#define F_ZETA  (1.05f)

typedef unsigned long long ull;

// packed f32x2 helpers (Blackwell: fma.rn.f32x2 is PTX-only, ptxas won't fuse)
#define PACKF2(d, x, y) \
    asm("mov.b64 %0, {%1,%2};" : "=l"(d) \
        : "r"(__float_as_uint(x)), "r"(__float_as_uint(y)))
#define UNPACKF2(x, y, d) do { unsigned _lo, _hi; \
    asm("mov.b64 {%0,%1}, %2;" : "=r"(_lo), "=r"(_hi) : "l"(d)); \
    (x) = __uint_as_float(_lo); (y) = __uint_as_float(_hi); } while (0)
#define FMAF2(d, a, b, c) \
    asm("fma.rn.f32x2 %0, %1, %2, %3;" : "=l"(d) : "l"(a), "l"(b), "l"(c))

// ---------------- scratch (__device__ globals; no allocs allowed) ---------
__device__ __half g_g1[NN * 64];   // fp16 attention operands
__device__ __half g_g2[NN * 64];
__device__ float  g_xa[NN * 64];
__device__ float  g_xb[NN * 64];
__device__ float  g_mask[EE];      // CSR order
__device__ float  g_dinv[NN];
__device__ int    g_rowptr[NN + 1];
__device__ int    g_wptr[NN];
__device__ int    g_count[NN];
__device__ int    g_ecol[EE];      // CSR col indices

// --------------------------- CSR build ------------------------------------
__global__ void hist_k(const int* __restrict__ row, int* __restrict__ count) {
    for (int e = blockIdx.x * blockDim.x + threadIdx.x; e < EE;
         e += gridDim.x * blockDim.x) atomicAdd(count + __ldg(row + e), 1);
}

__global__ void __launch_bounds__(1024) scan_k(const int* __restrict__ count,
                                               int* __restrict__ rowptr,
                                               int* __restrict__ wptr) {
    __shared__ int s[1024];
    int t = threadIdx.x;
    const int CH = (NN + 1023) / 1024;
    int beg = t * CH;
    int end = beg + CH; if (end > NN) end = NN;
    int sum = 0;
    for (int i = beg; i < end; i++) sum += count[i];
    s[t] = sum;
    __syncthreads();
    for (int o = 1; o < 1024; o <<= 1) {
        int v = s[t];
        if (t >= o) v += s[t - o];
        __syncthreads();
        s[t] = v;
        __syncthreads();
    }
    int run = (t == 0) ? 0 : s[t - 1];
    for (int i = beg; i < end; i++) {
        rowptr[i] = run;
        wptr[i]   = run;
        run += count[i];
    }
    if (t == 1023) rowptr[NN] = EE;
}

__global__ void scatter_k(const int* __restrict__ row, const int* __restrict__ col,
                          int* __restrict__ wptr, int* __restrict__ ecol) {
    for (int e = blockIdx.x * blockDim.x + threadIdx.x; e < EE;
         e += gridDim.x * blockDim.x) {
        int r = row[e];
        int p = atomicAdd(wptr + r, 1);
        ecol[p] = col[e];
    }
}

// --------- per-node MLPs: 8 nodes/warp, FFMA2 phase1, phased 32KB smem ----
__global__ void __launch_bounds__(256) node_kernel(
    const float* __restrict__ x,
    const float* __restrict__ nbW,  const float* __restrict__ nbb,
    const float* __restrict__ sfW,  const float* __restrict__ sfb,
    const float* __restrict__ a1W,  const float* __restrict__ a1b,
    __half* __restrict__ g1, __half* __restrict__ g2) {
    __shared__ float sA[4096];   // 16 KB
    __shared__ float sB[4096];   // 16 KB

    const unsigned FULL = 0xffffffffu;
    int tid  = threadIdx.x;
    int lane = tid & 31;
    int gtid = blockIdx.x * blockDim.x + tid;
    int gwarp = gtid >> 5;
    int base = gwarp * 8;

    // ---- phase 1 weights: nbW, sfW ----
    {
        const float4* a4 = (const float4*)nbW;
        const float4* b4 = (const float4*)sfW;
        for (int i = tid; i < 1024; i += 256) {
            ((float4*)sA)[i] = a4[i];
            ((float4*)sB)[i] = b4[i];
        }
    }
    __syncthreads();

    const float2* x2 = (const float2*)x;
    float2 xr[8];
    int   nid[8];
    bool  ok[8];
#pragma unroll
    for (int m = 0; m < 8; m++) {
        nid[m] = base + m;
        ok[m] = (nid[m] < NN);
        xr[m] = ok[m] ? x2[nid[m] * 32 + lane] : make_float2(0.f, 0.f);
    }

    // packed accumulators: f1[m] = (f1x, f1y), f2[m] = (f2x, f2y)
    ull f1[8], f2[8];
    {
        float2 bn = ((const float2*)nbb)[lane];
        float2 bs = ((const float2*)sfb)[lane];
#pragma unroll
        for (int m = 0; m < 8; m++) {
            PACKF2(f1[m], bn.x, bn.y);
            PACKF2(f2[m], bs.x, bs.y);
        }
    }
    const float2* sA2 = (const float2*)sA;
    const float2* sB2 = (const float2*)sB;
#pragma unroll 4
    for (int k = 0; k < 64; k++) {
        float2 wn = sA2[k * 32 + lane];
        float2 ws = sB2[k * 32 + lane];
        ull wn2, ws2;
        PACKF2(wn2, wn.x, wn.y);
        PACKF2(ws2, ws.x, ws.y);
#pragma unroll
        for (int m = 0; m < 8; m++) {
            float xv = __shfl_sync(FULL, (k & 1) ? xr[m].y : xr[m].x, k >> 1);
            ull xv2;
            PACKF2(xv2, xv, xv);
            FMAF2(f1[m], xv2, wn2, f1[m]);
            FMAF2(f2[m], xv2, ws2, f2[m]);
        }
    }
    float f1x[8], f1y[8], f2x[8], f2y[8];
#pragma unroll
    for (int m = 0; m < 8; m++) {
        UNPACKF2(f1x[m], f1y[m], f1[m]);
        UNPACKF2(f2x[m], f2y[m], f2[m]);
        f1x[m] = fmaxf(f1x[m], 0.f); f1y[m] = fmaxf(f1y[m], 0.f);
        f2x[m] = fmaxf(f2x[m], 0.f); f2y[m] = fmaxf(f2y[m], 0.f);
    }

    // ---- phase 2 weights: att1_W top/bot into the SAME smem ----
    __syncthreads();
    {
        const float4* t4 = (const float4*)a1W;
        const float4* b4 = (const float4*)(a1W + 4096);
        for (int i = tid; i < 1024; i += 256) {
            ((float4*)sA)[i] = t4[i];
            ((float4*)sB)[i] = b4[i];
        }
    }
    __syncthreads();

    float g1x[8], g1y[8], g2x[8], g2y[8];
    {
        float2 ab = ((const float2*)a1b)[lane];
#pragma unroll
        for (int m = 0; m < 8; m++) {
            g1x[m] = 0.f; g1y[m] = 0.f;
            g2x[m] = ab.x; g2y[m] = ab.y;
        }
    }
#pragma unroll 4
    for (int k = 0; k < 64; k++) {
        float2 wt = sA2[k * 32 + lane];
        float2 wb = sB2[k * 32 + lane];
#pragma unroll
        for (int m = 0; m < 8; m++) {
            float u = __shfl_sync(FULL, (k & 1) ? f1y[m] : f1x[m], k >> 1);
            float v = __shfl_sync(FULL, (k & 1) ? f2y[m] : f2x[m], k >> 1);
            g1x[m] += u * wt.x; g1y[m] += u * wt.y;
            g2x[m] += v * wb.x; g2y[m] += v * wb.y;
        }
    }

#pragma unroll
    for (int m = 0; m < 8; m++) {
        if (!ok[m]) continue;
        ((__half2*)g1)[nid[m] * 32 + lane] = __floats2half2_rn(g1x[m], g1y[m]);
        ((__half2*)g2)[nid[m] * 32 + lane] = __floats2half2_rn(g2x[m], g2y[m]);
    }
}

// ---- attention: CSR warp-per-row, 2 edges/iter, half2 math throughout ----
__global__ void __launch_bounds__(256) attn_k(
    const __half* __restrict__ g1, const __half* __restrict__ g2,
    const float* __restrict__ a2W, const float* __restrict__ a2b,
    const int* __restrict__ rowptr, const int* __restrict__ ecol,
    float* __restrict__ mask, float* __restrict__ dinv) {
    int lane = threadIdx.x & 31;
    int half = lane >> 4;
    int ln   = lane & 15;
    unsigned hm = 0xFFFFu << (half << 4);
    int r = (blockIdx.x * blockDim.x + threadIdx.x) >> 5;
    if (r >= NN) return;

    float4 w = ((const float4*)a2W)[ln];
    __half2 w01 = __floats2half2_rn(w.x, w.y);
    __half2 w23 = __floats2half2_rn(w.z, w.w);
    __half2 hz  = __float2half2_rn(0.f);
    float bias = a2b[0];

    const uint2* g1v = (const uint2*)g1;
    const uint2* g2v = (const uint2*)g2;
    uint2 ar = g1v[r * 16 + ln];
    __half2 a0 = *(const __half2*)&ar.x;
    __half2 a1 = *(const __half2*)&ar.y;

    int p0 = __ldg(rowptr + r), p1 = __ldg(rowptr + r + 1);
    float rs = 0.f;
#pragma unroll 4
    for (int p = p0 + half; p < p1; p += 2) {
        int c = __ldg(ecol + p);
        uint2 br = g2v[c * 16 + ln];
        __half2 t0 = __hmax2(__hadd2(a0, *(const __half2*)&br.x), hz);
        __half2 t1 = __hmax2(__hadd2(a1, *(const __half2*)&br.y), hz);
        __half2 acc = __hfma2(t0, w01, __hmul2(t1, w23));
        float s = __low2float(acc) + __high2float(acc);
        s += __shfl_xor_sync(hm, s, 8);
        s += __shfl_xor_sync(hm, s, 4);
        s += __shfl_xor_sync(hm, s, 2);
        s += __shfl_xor_sync(hm, s, 1);
        float sig = __fdividef(1.f, 1.f + __expf(-(s + bias)));
        float mk  = fminf(fmaxf(sig * (F_ZETA - F_GAMMA) + F_GAMMA, 0.f), 1.f);
        if (ln == 0) mask[p] = mk;
        rs += mk;
    }
    rs += __shfl_xor_sync(0xffffffffu, rs, 16);
    if (lane == 0) dinv[r] = fminf(rsqrtf(rs + 1e-6f), 10.f);
}

// -- SpMM CSR: 8-lane quarter-warps, 4 edges/iter, f32x2, fused epilogue ---
// Lane ln (0..7) owns features {4ln..4ln+3} and {32+4ln..32+4ln+3}.
__global__ void __launch_bounds__(256) spmm_k(
    const float* __restrict__ x, const float* __restrict__ mask,
    const float* __restrict__ dinv,
    const int* __restrict__ rowptr, const int* __restrict__ ecol,
    float* __restrict__ xnew, const float* __restrict__ base,
    float* __restrict__ out) {
    const unsigned FULL = 0xffffffffu;
    int lane = threadIdx.x & 31;
    int grp  = lane >> 3;        // 0..3: edge subgroup
    int ln   = lane & 7;         // 0..7: feature owner
    int r = (blockIdx.x * blockDim.x + threadIdx.x) >> 5;
    if (r >= NN) return;

    const ulonglong2* x16 = (const ulonglong2*)x;   // 16B chunks, 16 per row
    int p0 = __ldg(rowptr + r), p1 = __ldg(rowptr + r + 1);
    ull a0 = 0ull, a1 = 0ull, a2 = 0ull, a3 = 0ull;
#pragma unroll 2
    for (int p = p0 + grp; p < p1; p += 4) {
        int c = __ldg(ecol + p);
        float v = __ldg(mask + p) * __ldg(dinv + c);
        ull v2;
        PACKF2(v2, v, v);
        ulonglong2 xv0 = x16[c * 16 + ln];       // bytes [16ln, 16ln+16)
        ulonglong2 xv1 = x16[c * 16 + 8 + ln];   // bytes [128+16ln, ...)
        FMAF2(a0, v2, xv0.x, a0);
        FMAF2(a1, v2, xv0.y, a1);
        FMAF2(a2, v2, xv1.x, a2);
        FMAF2(a3, v2, xv1.y, a3);
    }
    float f[8];
    UNPACKF2(f[0], f[1], a0);
    UNPACKF2(f[2], f[3], a1);
    UNPACKF2(f[4], f[5], a2);
    UNPACKF2(f[6], f[7], a3);
#pragma unroll
    for (int i = 0; i < 8; i++) {
        f[i] += __shfl_xor_sync(FULL, f[i], 8);
        f[i] += __shfl_xor_sync(FULL, f[i], 16);
    }
    if (grp == 0) {
        float dr = __ldg(dinv + r);
        float4 r0 = make_float4(f[0] * dr, f[1] * dr, f[2] * dr, f[3] * dr);
        float4 r1 = make_float4(f[4] * dr, f[5] * dr, f[6] * dr, f[7] * dr);
        ((float4*)xnew)[r * 16 + ln]     = r0;
        ((float4*)xnew)[r * 16 + 8 + ln] = r1;
        float4 b0 = ((const float4*)base)[r * 16 + ln];
        float4 b1 = ((const float4*)base)[r * 16 + 8 + ln];
        b0.x += r0.x; b0.y += r0.y; b0.z += r0.z; b0.w += r0.w;
        b1.x += r1.x; b1.y += r1.y; b1.z += r1.z; b1.w += r1.w;
        ((float4*)out)[r * 16 + ln]     = b0;
        ((float4*)out)[r * 16 + 8 + ln] = b1;
    }
}

extern "C" void kernel_launch(void* const* d_in, const int* in_sizes, int n_in,
                              void* d_out, int out_size) {
    const float* features = (const float*)d_in[0];
    const float* nb_W     = (const float*)d_in[1];
    const float* nb_b     = (const float*)d_in[2];
    const float* self_W   = (const float*)d_in[3];
    const float* self_b   = (const float*)d_in[4];
    const float* att1_W   = (const float*)d_in[5];
    const float* att1_b   = (const float*)d_in[6];
    const float* att2_W   = (const float*)d_in[7];
    const float* att2_b   = (const float*)d_in[8];
    const int*   row      = (const int*)d_in[9];
    const int*   col      = (const int*)d_in[10];
    float* out = (float*)d_out;

    __half *g1, *g2;
    float *xa, *xb, *mask, *dinv;
    int *rowptr, *wptr, *count, *ecol;
    cudaGetSymbolAddress((void**)&g1,     g_g1);
    cudaGetSymbolAddress((void**)&g2,     g_g2);
    cudaGetSymbolAddress((void**)&xa,     g_xa);
    cudaGetSymbolAddress((void**)&xb,     g_xb);
    cudaGetSymbolAddress((void**)&mask,   g_mask);
    cudaGetSymbolAddress((void**)&dinv,   g_dinv);
    cudaGetSymbolAddress((void**)&rowptr, g_rowptr);
    cudaGetSymbolAddress((void**)&wptr,   g_wptr);
    cudaGetSymbolAddress((void**)&count,  g_count);
    cudaGetSymbolAddress((void**)&ecol,   g_ecol);

    cudaMemsetAsync(count, 0, NN * sizeof(int));   // not a kernel launch

    const float* xin[3]  = { features, xa, xb };
    float*       xout[3] = { xa, xb, xa };

    // kernels 0,1,2: CSR build
    hist_k<<<2048, 256>>>(row, count);
    scan_k<<<1, 1024>>>(count, rowptr, wptr);
    scatter_k<<<2048, 256>>>(row, col, wptr, ecol);

    for (int l = 0; l < 3; l++) {
        // l==0: kernel index 3 -> profiled (first look at FFMA2 node)
        node_kernel<<<1563, 256>>>(xin[l],
            nb_W + l * 4096,   nb_b + l * 64,
            self_W + l * 4096, self_b + l * 64,
            att1_W + l * 8192, att1_b + l * 64,
            g1, g2);
        attn_k<<<12500, 256>>>(g1, g2, att2_W + l * 64, att2_b + l,
                               rowptr, ecol, mask, dinv);
        spmm_k<<<12500, 256>>>(xin[l], mask, dinv, rowptr, ecol,
                               xout[l], (l == 0) ? features : out, out);
    }
}